// round 5
// baseline (speedup 1.0000x reference)
#include <cuda_runtime.h>
#include <cstdint>
#include <math.h>

// ---------------- Problem constants ----------------
#define BB   256
#define NH   850
#define TT   70
#define PK   864            // padded K for states (27*32)
#define PK0  1728           // padded K for [x, h]  (54*32)
#define WNC  1728           // prepped weight row: [0,864)=c cols, [864,1728)=h cols
#define NCTA 296            // 2 CTAs per SM x 148 SMs
#define NTHR 128

// ---------------- Global scratch (static; no allocs) ----------------
__device__ __align__(16) float g_states[9][BB * PK];
__device__ __align__(16) float g_xh[BB * PK0];
__device__ __align__(16) float g_w0[(size_t)PK0 * WNC];
__device__ __align__(16) float g_we[8][(size_t)PK * WNC];

__device__ unsigned g_cnt = 0;
__device__ volatile unsigned g_sense = 0;

struct Edge { int pred, out, w, act; };
__constant__ Edge c_edges[8] = {
    {0, 1, 0, 0}, {1, 2, 1, 1}, {1, 3, 2, 1}, {1, 4, 3, 3},
    {2, 5, 4, 0}, {5, 6, 5, 2}, {3, 7, 6, 0}, {5, 8, 7, 1},
};
// DAG levels over edges
__constant__ int c_lvl_n[4]    = {1, 3, 2, 2};
__constant__ int c_lvl_e[4][3] = {{0,0,0}, {1,2,3}, {4,6,0}, {5,7,0}};

// ---------------- Helpers ----------------
__device__ __forceinline__ uint32_t cvt_tf32(float x) {
    uint32_t u;
    asm("cvt.rna.tf32.f32 %0, %1;" : "=r"(u) : "f"(x));
    return u;
}
__device__ __forceinline__ float tf32r(float x) { return __uint_as_float(cvt_tf32(x)); }

__device__ __forceinline__ void cp16(void* dst, const void* src) {
    uint32_t d = (uint32_t)__cvta_generic_to_shared(dst);
    asm volatile("cp.async.cg.shared.global [%0], [%1], 16;" :: "r"(d), "l"(src) : "memory");
}
__device__ __forceinline__ void cp_commit() {
    asm volatile("cp.async.commit_group;" ::: "memory");
}
template <int N> __device__ __forceinline__ void cp_wait() {
    asm volatile("cp.async.wait_group %0;" :: "n"(N) : "memory");
}
__device__ __forceinline__ void mma8(float* d, const uint32_t* a, uint32_t b0, uint32_t b1) {
    asm volatile("mma.sync.aligned.m16n8k8.row.col.f32.tf32.tf32.f32 "
        "{%0,%1,%2,%3}, {%4,%5,%6,%7}, {%8,%9}, {%0,%1,%2,%3};"
        : "+f"(d[0]), "+f"(d[1]), "+f"(d[2]), "+f"(d[3])
        : "r"(a[0]), "r"(a[1]), "r"(a[2]), "r"(a[3]), "r"(b0), "r"(b1));
}
__device__ __forceinline__ float actf(float x, int a) {
    if (a == 0) return tanhf(x);
    if (a == 1) return fmaxf(x, 0.f);
    if (a == 2) return 1.f / (1.f + __expf(-x));
    return x;
}

// ---------------- Grid-wide barrier (sense-reversing, replay-safe) ----------------
__device__ __forceinline__ void grid_sync(unsigned* sense) {
    __syncthreads();
    if (threadIdx.x == 0) {
        unsigned s = *sense + 1;
        *sense = s;
        __threadfence();
        unsigned arr = atomicAdd(&g_cnt, 1u);
        if (arr == (unsigned)NCTA - 1) {
            g_cnt = 0;
            __threadfence();
            g_sense = s;
        } else {
            while (g_sense != s) { __nanosleep(64); }
        }
        __threadfence();
    }
    __syncthreads();
}

// ---------------- One GEMM tile: 64 rows x 32 col-pairs, fused highway epilogue ----------------
__device__ __forceinline__ void load_stage(
    float (*As)[64][36], float (*Bs)[32][72], int s, int kt,
    const float* __restrict__ A, int strideA, const float* __restrict__ W,
    int m0, int j0, int tid)
{
    const int k0 = kt * 32;
    #pragma unroll
    for (int i = 0; i < 4; i++) {
        int idx = tid + i * 128;
        int r = idx >> 3, c = idx & 7;
        cp16(&As[s][r][c * 4], A + (size_t)(m0 + r) * strideA + k0 + c * 4);
    }
    #pragma unroll
    for (int i = 0; i < 4; i++) {
        int idx = tid + i * 128;
        int kk = idx >> 4, c = idx & 15;
        const float* src = W + (size_t)(k0 + kk) * WNC
                             + (c < 8 ? (j0 + c * 4) : (864 + j0 + (c - 8) * 4));
        cp16(&Bs[s][kk][c * 4], src);
    }
}

__device__ __forceinline__ void gemm_tile(
    const float* __restrict__ A, int strideA, const float* __restrict__ W,
    const float* __restrict__ P, int strideP, float* __restrict__ Out,
    int act, int niter, int m0, int j0)
{
    __shared__ float As[2][64][36];
    __shared__ float Bs[2][32][72];

    const int tid = threadIdx.x, wid = tid >> 5, lid = tid & 31;
    const int wm = wid & 1, wn = wid >> 1;
    const int lr = lid >> 2, lc = lid & 3;

    float cacc[2][2][4], hacc[2][2][4];
    #pragma unroll
    for (int a = 0; a < 2; a++)
        #pragma unroll
        for (int b = 0; b < 2; b++)
            #pragma unroll
            for (int c = 0; c < 4; c++) { cacc[a][b][c] = 0.f; hacc[a][b][c] = 0.f; }

    load_stage(As, Bs, 0, 0, A, strideA, W, m0, j0, tid);
    cp_commit();

    for (int it = 0; it < niter; it++) {
        const int buf = it & 1;
        if (it + 1 < niter) {
            load_stage(As, Bs, buf ^ 1, it + 1, A, strideA, W, m0, j0, tid);
            cp_commit();
            cp_wait<1>();
        } else {
            cp_wait<0>();
        }
        __syncthreads();

        #pragma unroll
        for (int ks = 0; ks < 4; ks++) {
            uint32_t af[2][4];
            const int k = ks * 8 + lc;
            #pragma unroll
            for (int mf = 0; mf < 2; mf++) {
                int r = wm * 32 + mf * 16 + lr;
                af[mf][0] = cvt_tf32(As[buf][r][k]);
                af[mf][1] = cvt_tf32(As[buf][r + 8][k]);
                af[mf][2] = cvt_tf32(As[buf][r][k + 4]);
                af[mf][3] = cvt_tf32(As[buf][r + 8][k + 4]);
            }
            #pragma unroll
            for (int nf = 0; nf < 2; nf++) {
                int col = wn * 16 + nf * 8 + lr;
                uint32_t bc0 = __float_as_uint(Bs[buf][k][col]);
                uint32_t bc1 = __float_as_uint(Bs[buf][k + 4][col]);
                uint32_t bh0 = __float_as_uint(Bs[buf][k][col + 32]);
                uint32_t bh1 = __float_as_uint(Bs[buf][k + 4][col + 32]);
                #pragma unroll
                for (int mf = 0; mf < 2; mf++) {
                    mma8(cacc[mf][nf], af[mf], bc0, bc1);
                    mma8(hacc[mf][nf], af[mf], bh0, bh1);
                }
            }
        }
        __syncthreads();
    }

    #pragma unroll
    for (int mf = 0; mf < 2; mf++) {
        #pragma unroll
        for (int nf = 0; nf < 2; nf++) {
            const int r0 = m0 + wm * 32 + mf * 16 + lr;
            const int c0 = j0 + wn * 16 + nf * 8 + lc * 2;
            #pragma unroll
            for (int e = 0; e < 4; e++) {
                int r = r0 + (e >> 1) * 8;
                int c = c0 + (e & 1);
                if (c < NH) {
                    float sp = P[(size_t)r * strideP + c];
                    float g  = 1.f / (1.f + __expf(-cacc[mf][nf][e]));
                    float av = actf(hacc[mf][nf][e], act);
                    Out[(size_t)r * PK + c] = sp + g * (av - sp);
                }
            }
        }
    }
}

// ---------------- Persistent kernel: entire 70-step recurrence ----------------
__global__ __launch_bounds__(NTHR, 2) void step_kernel(
    const float* __restrict__ inputs, const float* __restrict__ hidden,
    float* __restrict__ out)
{
    unsigned sense = g_sense;   // snapshot (monotonic counter; replay-safe)
    const int cta = blockIdx.x;
    const int gtid = cta * NTHR + threadIdx.x;

    // Initial staging: x0 and h0 into padded [x | h] buffer
    for (int i = gtid; i < BB * NH; i += NCTA * NTHR) {
        int b = i / NH, j = i % NH;
        g_xh[b * PK0 + j]      = inputs[i];
        g_xh[b * PK0 + PK + j] = hidden[i];
    }
    grid_sync(&sense);

    for (int t = 0; t < TT; t++) {
        // Level 0: s0 = highway([x,h] @ W0), K = 1728, 108 tiles
        for (int tl = cta; tl < 108; tl += NCTA) {
            int mt = tl / 27, nt = tl % 27;
            gemm_tile(g_xh, PK0, g_w0, g_xh + PK, PK0, g_states[0], 0, 54,
                      mt * 64, nt * 32);
        }
        grid_sync(&sense);

        // Levels 1..4: edge GEMMs, K = 864
        #pragma unroll
        for (int L = 0; L < 4; L++) {
            const int ntile = c_lvl_n[L] * 108;
            for (int tl = cta; tl < ntile; tl += NCTA) {
                int e = tl / 108, r = tl % 108;
                int mt = r / 27, nt = r % 27;
                Edge E = c_edges[c_lvl_e[L][e]];
                gemm_tile(g_states[E.pred], PK, g_we[E.w],
                          g_states[E.pred], PK, g_states[E.out], E.act, 27,
                          mt * 64, nt * 32);
            }
            grid_sync(&sense);
        }

        // mean over s1..s8 -> out[t], stage next x/h
        for (int i = gtid; i < BB * NH; i += NCTA * NTHR) {
            int b = i / NH, j = i % NH;
            float s = 0.f;
            #pragma unroll
            for (int st = 1; st < 9; st++) s += g_states[st][b * PK + j];
            s *= 0.125f;
            out[(size_t)t * (BB * NH) + i] = s;
            g_xh[b * PK0 + PK + j] = s;
            if (t + 1 < TT) g_xh[b * PK0 + j] = inputs[(size_t)(t + 1) * (BB * NH) + i];
            else            out[(size_t)TT * (BB * NH) + i] = s;   // hiddens[-1]
        }
        grid_sync(&sense);
    }
}

// ---------------- Weight prep (padded, c/h-paired, tf32-rounded) ----------------
__global__ void prep_w0(const float* __restrict__ W0) {
    size_t i = (size_t)blockIdx.x * blockDim.x + threadIdx.x;
    if (i >= (size_t)PK0 * WNC) return;
    int k = (int)(i / WNC), n = (int)(i % WNC);
    int kr = (k < NH) ? k : ((k >= PK && k < PK + NH) ? (NH + k - PK) : -1);
    int nc = (n < 864) ? ((n < NH) ? n : -1)
                       : ((n - 864 < NH) ? (NH + n - 864) : -1);
    float v = 0.f;
    if (kr >= 0 && nc >= 0) v = W0[(size_t)kr * (2 * NH) + nc];
    g_w0[i] = tf32r(v);
}
__global__ void prep_we(const float* __restrict__ Ws) {
    size_t i = (size_t)blockIdx.x * blockDim.x + threadIdx.x;
    if (i >= (size_t)8 * PK * WNC) return;
    int e = (int)(i / ((size_t)PK * WNC));
    size_t r = i % ((size_t)PK * WNC);
    int k = (int)(r / WNC), n = (int)(r % WNC);
    int nc = (n < 864) ? ((n < NH) ? n : -1)
                       : ((n - 864 < NH) ? (NH + n - 864) : -1);
    float v = 0.f;
    if (k < NH && nc >= 0) v = Ws[((size_t)e * NH + k) * (2 * NH) + nc];
    g_we[e][(size_t)k * WNC + n] = tf32r(v);
}

// ---------------- Zero padding + barrier state ----------------
__global__ void zero_kernel() {
    int i = blockIdx.x * blockDim.x + threadIdx.x;
    if (i == 0) g_cnt = 0;
    if (i < 9 * BB * PK) (&g_states[0][0])[i] = 0.f;
    if (i < BB * PK0)    g_xh[i] = 0.f;
}

// ---------------- Host ----------------
extern "C" void kernel_launch(void* const* d_in, const int* in_sizes, int n_in,
                              void* d_out, int out_size)
{
    const float* inputs = (const float*)d_in[0];  // [T, B, NH]
    const float* hidden = (const float*)d_in[1];  // [1, B, NH]
    const float* W0     = (const float*)d_in[2];  // [2*NH, 2*NH]
    const float* Ws     = (const float*)d_in[3];  // [8, NH, 2*NH]
    float* out = (float*)d_out;

    zero_kernel<<<(9 * BB * PK + 255) / 256, 256>>>();
    prep_w0<<<(int)(((size_t)PK0 * WNC + 255) / 256), 256>>>(W0);
    prep_we<<<(int)(((size_t)8 * PK * WNC + 255) / 256), 256>>>(Ws);

    step_kernel<<<NCTA, NTHR>>>(inputs, hidden, out);
}